// round 4
// baseline (speedup 1.0000x reference)
#include <cuda_runtime.h>
#include <cuda_bf16.h>

typedef __nv_bfloat16 bf16;

#define DM     256
#define TT     8
#define NH     4
#define DHD    64
#define NQKV   768
#define NBATCH 32768
#define MROWS  262144   // NBATCH * TT

// ---------------- scratch (device globals: allocation-free rule) ----------------
__device__ bf16  g_Wqkv_hi[DM * NQKV];
__device__ bf16  g_Wqkv_lo[DM * NQKV];
__device__ float g_bqkv[NQKV];
__device__ bf16  g_Wfc_hi[DM * DM];
__device__ bf16  g_Wfc_lo[DM * DM];
__device__ bf16  g_Xhi[(size_t)MROWS * DM];
__device__ bf16  g_Xlo[(size_t)MROWS * DM];
__device__ float g_QKV[(size_t)MROWS * NQKV];
__device__ bf16  g_Ohi[(size_t)MROWS * DM];
__device__ bf16  g_Olo[(size_t)MROWS * DM];

// ---------------- weight prep: build Wqkv [256,768] (q|k|v, head-major cols), split hi/lo ----------------
__global__ void prep_w_kernel(const float* __restrict__ Wq, const float* __restrict__ bq,
                              const float* __restrict__ Wk, const float* __restrict__ bk,
                              const float* __restrict__ Wv, const float* __restrict__ bv,
                              const float* __restrict__ Wfc)
{
    int i = blockIdx.x * blockDim.x + threadIdx.x;
    int stride = gridDim.x * blockDim.x;
    for (int idx = i; idx < DM * NQKV; idx += stride) {
        int d = idx / NQKV, j = idx % NQKV;
        int sec = j >> 8;            // 0=q,1=k,2=v
        int h = (j & 255) >> 6;
        int e = j & 63;
        const float* W = (sec == 0) ? Wq : ((sec == 1) ? Wk : Wv);
        float w = W[(h * DM + d) * DHD + e];
        bf16 hi = __float2bfloat16(w);
        g_Wqkv_hi[idx] = hi;
        g_Wqkv_lo[idx] = __float2bfloat16(w - __bfloat162float(hi));
    }
    for (int idx = i; idx < DM * DM; idx += stride) {
        float w = Wfc[idx];
        bf16 hi = __float2bfloat16(w);
        g_Wfc_hi[idx] = hi;
        g_Wfc_lo[idx] = __float2bfloat16(w - __bfloat162float(hi));
    }
    for (int idx = i; idx < NQKV; idx += stride) {
        int sec = idx >> 8;
        int h = (idx & 255) >> 6;
        int e = idx & 63;
        const float* bsrc = (sec == 0) ? bq : ((sec == 1) ? bk : bv);
        g_bqkv[idx] = bsrc[h * DHD + e];
    }
}

// ---------------- x -> hi/lo split ----------------
__global__ void split_x_kernel(const float* __restrict__ x)
{
    size_t stride = (size_t)gridDim.x * blockDim.x;
    for (size_t idx = (size_t)blockIdx.x * blockDim.x + threadIdx.x;
         idx < (size_t)MROWS * DM; idx += stride) {
        float v = x[idx];
        bf16 hi = __float2bfloat16(v);
        g_Xhi[idx] = hi;
        g_Xlo[idx] = __float2bfloat16(v - __bfloat162float(hi));
    }
}

// ---------------- mma.sync bf16 helper ----------------
__device__ __forceinline__ void mma_bf16(float c[4], const unsigned a[4], unsigned b0, unsigned b1)
{
    asm volatile(
        "mma.sync.aligned.m16n8k16.row.col.f32.bf16.bf16.f32 "
        "{%0,%1,%2,%3}, {%4,%5,%6,%7}, {%8,%9}, {%0,%1,%2,%3};\n"
        : "+f"(c[0]), "+f"(c[1]), "+f"(c[2]), "+f"(c[3])
        : "r"(a[0]), "r"(a[1]), "r"(a[2]), "r"(a[3]), "r"(b0), "r"(b1));
}

// ---------------- split-3 GEMM: C[M,NTOT] = A(hi+lo) @ B(hi+lo) + bias ----------------
// CTA tile 128x128, K-chunks of 64, 8 warps (4 M x 2 N), warp tile 32x64.
#define SROW 72   // padded smem row (halves) for 64-wide k-chunk
#define SMEM_GEMM_BYTES (4 * 128 * SROW * 2)

template<int NTOT, bool FIRST>
__global__ void __launch_bounds__(256)
gemm_split3_kernel(const float* __restrict__ bias_in, float* __restrict__ C_out)
{
    extern __shared__ bf16 smem[];
    bf16* sAh = smem;
    bf16* sAl = sAh + 128 * SROW;
    bf16* sBh = sAl + 128 * SROW;
    bf16* sBl = sBh + 128 * SROW;

    const bf16* __restrict__ Ah = FIRST ? g_Xhi : g_Ohi;
    const bf16* __restrict__ Al = FIRST ? g_Xlo : g_Olo;
    const bf16* __restrict__ Bh = FIRST ? g_Wqkv_hi : g_Wfc_hi;
    const bf16* __restrict__ Bl = FIRST ? g_Wqkv_lo : g_Wfc_lo;
    const float* __restrict__ bias = FIRST ? g_bqkv : bias_in;
    float* __restrict__ C = FIRST ? g_QKV : C_out;

    const int tid = threadIdx.x;
    const int warp = tid >> 5, lane = tid & 31;
    const int gid = lane >> 2, tig = lane & 3;
    const int wm = (warp & 3) * 32;
    const int wn = (warp >> 2) * 64;
    const size_t m0 = (size_t)blockIdx.y * 128;
    const int n0 = blockIdx.x * 128;

    float acc[2][8][4];
    #pragma unroll
    for (int a = 0; a < 2; a++)
        #pragma unroll
        for (int b = 0; b < 8; b++)
            #pragma unroll
            for (int c = 0; c < 4; c++) acc[a][b][c] = 0.f;

    for (int kc = 0; kc < DM; kc += 64) {
        // stage A tile [128 x 64] hi/lo (32-bit copies, k-contiguous)
        #pragma unroll
        for (int u = tid; u < 4096; u += 256) {
            int row = u >> 5;
            int kk = (u & 31) * 2;
            size_t g = (m0 + row) * DM + kc + kk;
            *(unsigned*)&sAh[row * SROW + kk] = *(const unsigned*)&Ah[g];
            *(unsigned*)&sAl[row * SROW + kk] = *(const unsigned*)&Al[g];
        }
        // stage B transposed: sB[n][k] = W[kc+k][n0+n]
        #pragma unroll
        for (int u = tid; u < 8192; u += 256) {
            int k = u >> 7;
            int n = u & 127;
            size_t g = (size_t)(kc + k) * NTOT + n0 + n;
            sBh[n * SROW + k] = Bh[g];
            sBl[n * SROW + k] = Bl[g];
        }
        __syncthreads();

        #pragma unroll
        for (int ks = 0; ks < 4; ks++) {
            const int kb = ks * 16 + tig * 2;
            unsigned ah[2][4], al[2][4];
            #pragma unroll
            for (int mt = 0; mt < 2; mt++) {
                int r = wm + mt * 16 + gid;
                ah[mt][0] = *(unsigned*)&sAh[r * SROW + kb];
                ah[mt][1] = *(unsigned*)&sAh[(r + 8) * SROW + kb];
                ah[mt][2] = *(unsigned*)&sAh[r * SROW + kb + 8];
                ah[mt][3] = *(unsigned*)&sAh[(r + 8) * SROW + kb + 8];
                al[mt][0] = *(unsigned*)&sAl[r * SROW + kb];
                al[mt][1] = *(unsigned*)&sAl[(r + 8) * SROW + kb];
                al[mt][2] = *(unsigned*)&sAl[r * SROW + kb + 8];
                al[mt][3] = *(unsigned*)&sAl[(r + 8) * SROW + kb + 8];
            }
            #pragma unroll
            for (int nt = 0; nt < 8; nt++) {
                int n = wn + nt * 8 + gid;
                unsigned bh0 = *(unsigned*)&sBh[n * SROW + kb];
                unsigned bh1 = *(unsigned*)&sBh[n * SROW + kb + 8];
                unsigned bl0 = *(unsigned*)&sBl[n * SROW + kb];
                unsigned bl1 = *(unsigned*)&sBl[n * SROW + kb + 8];
                #pragma unroll
                for (int mt = 0; mt < 2; mt++) {
                    mma_bf16(acc[mt][nt], ah[mt], bh0, bh1);  // hi*hi
                    mma_bf16(acc[mt][nt], ah[mt], bl0, bl1);  // hi*lo
                    mma_bf16(acc[mt][nt], al[mt], bh0, bh1);  // lo*hi
                }
            }
        }
        __syncthreads();
    }

    // epilogue: + bias, fp32 store
    #pragma unroll
    for (int mt = 0; mt < 2; mt++) {
        #pragma unroll
        for (int nt = 0; nt < 8; nt++) {
            int cn = n0 + wn + nt * 8 + tig * 2;
            float b0 = bias[cn], b1 = bias[cn + 1];
            size_t r = m0 + wm + mt * 16 + gid;
            float2 v0 = make_float2(acc[mt][nt][0] + b0, acc[mt][nt][1] + b1);
            float2 v1 = make_float2(acc[mt][nt][2] + b0, acc[mt][nt][3] + b1);
            *(float2*)&C[r * NTOT + cn] = v0;
            *(float2*)&C[(r + 8) * NTOT + cn] = v1;
        }
    }
}

// ---------------- tiny causal attention: one warp per (batch, head) ----------------
__global__ void __launch_bounds__(128) attn_kernel()
{
    __shared__ float sq[4][TT][64];
    __shared__ float sk[4][TT][68];
    __shared__ float sv[4][TT][68];
    __shared__ float sw[4][TT][TT];

    const int warp = threadIdx.x >> 5, lane = threadIdx.x & 31;
    const int task = blockIdx.x * 4 + warp;
    const int b = task >> 2, h = task & 3;

    const float* base = g_QKV + (size_t)b * TT * NQKV + h * DHD;
    for (int f = lane; f < 128; f += 32) {
        int t = f >> 4;
        int c = (f & 15) * 4;
        *(float4*)&sq[warp][t][c] = *(const float4*)&base[t * NQKV + c];
        *(float4*)&sk[warp][t][c] = *(const float4*)&base[t * NQKV + 256 + c];
        *(float4*)&sv[warp][t][c] = *(const float4*)&base[t * NQKV + 512 + c];
    }
    __syncwarp();

    const int t = lane >> 2;
    const int sb = lane & 3;
    float sc[2];
    #pragma unroll
    for (int j = 0; j < 2; j++) {
        int s = sb + j * 4;
        if (s <= t) {
            float d = 0.f;
            #pragma unroll
            for (int e = 0; e < 64; e++) d += sq[warp][t][e] * sk[warp][s][e];
            sc[j] = d * 0.125f;  // 1/sqrt(64)
        } else {
            sc[j] = -1e30f;
        }
    }
    float m = fmaxf(sc[0], sc[1]);
    m = fmaxf(m, __shfl_xor_sync(0xffffffffu, m, 1));
    m = fmaxf(m, __shfl_xor_sync(0xffffffffu, m, 2));
    float e0 = (sb     <= t) ? __expf(sc[0] - m) : 0.f;
    float e1 = (sb + 4 <= t) ? __expf(sc[1] - m) : 0.f;
    float sum = e0 + e1;
    sum += __shfl_xor_sync(0xffffffffu, sum, 1);
    sum += __shfl_xor_sync(0xffffffffu, sum, 2);
    float inv = 1.0f / sum;
    sw[warp][t][sb]     = e0 * inv;
    sw[warp][t][sb + 4] = e1 * inv;
    __syncwarp();

    float w[TT];
    #pragma unroll
    for (int s = 0; s < TT; s++) w[s] = sw[warp][t][s];
    const int cb = sb * 16;
    const size_t orow = ((size_t)b * TT + t) * DM + h * DHD + cb;
    #pragma unroll
    for (int c = 0; c < 16; c++) {
        float o = 0.f;
        #pragma unroll
        for (int s = 0; s < TT; s++) o += w[s] * sv[warp][s][cb + c];
        bf16 hi = __float2bfloat16(o);
        g_Ohi[orow + c] = hi;
        g_Olo[orow + c] = __float2bfloat16(o - __bfloat162float(hi));
    }
}

// ---------------- launch ----------------
extern "C" void kernel_launch(void* const* d_in, const int* in_sizes, int n_in,
                              void* d_out, int out_size)
{
    const float* x   = (const float*)d_in[0];
    const float* Wq  = (const float*)d_in[1];
    const float* bq  = (const float*)d_in[2];
    const float* Wk  = (const float*)d_in[3];
    const float* bk  = (const float*)d_in[4];
    const float* Wv  = (const float*)d_in[5];
    const float* bv  = (const float*)d_in[6];
    const float* Wfc = (const float*)d_in[7];
    const float* bfc = (const float*)d_in[8];
    float* out = (float*)d_out;

    cudaFuncSetAttribute(gemm_split3_kernel<NQKV, true>,
                         cudaFuncAttributeMaxDynamicSharedMemorySize, SMEM_GEMM_BYTES);
    cudaFuncSetAttribute(gemm_split3_kernel<DM, false>,
                         cudaFuncAttributeMaxDynamicSharedMemorySize, SMEM_GEMM_BYTES);

    prep_w_kernel<<<192, 256>>>(Wq, bq, Wk, bk, Wv, bv, Wfc);
    split_x_kernel<<<8192, 256>>>(x);

    // GEMM1: QKV = Xsplit @ Wqkv + bqkv ; grid x = N-blocks (fastest) for A-tile L2 reuse
    gemm_split3_kernel<NQKV, true>
        <<<dim3(NQKV / 128, MROWS / 128), 256, SMEM_GEMM_BYTES>>>(nullptr, nullptr);

    // attention: 4 (batch,head) tasks per CTA
    attn_kernel<<<(NBATCH * NH) / 4, 128>>>();

    // GEMM2: out = Osplit @ Wfc + bfc
    gemm_split3_kernel<DM, false>
        <<<dim3(DM / 128, MROWS / 128), 256, SMEM_GEMM_BYTES>>>(bfc, out);
}

// round 5
// speedup vs baseline: 2.3980x; 2.3980x over previous
#include <cuda_runtime.h>
#include <cuda_bf16.h>

typedef __nv_bfloat16 bf16;

#define DM     256
#define TT     8
#define NH     4
#define DHD    64
#define NQKV   768
#define NBATCH 32768
#define MROWS  262144   // NBATCH * TT

// ---------------- scratch (device globals: allocation-free rule) ----------------
// Weights stored TRANSPOSED: [n][k] (k contiguous) so GEMM B staging is plain copies.
__device__ bf16  g_Wqkv_hi[NQKV * DM];
__device__ bf16  g_Wqkv_lo[NQKV * DM];
__device__ float g_bqkv[NQKV];
__device__ bf16  g_Wfc_hi[DM * DM];
__device__ bf16  g_Wfc_lo[DM * DM];
__device__ float g_QKV[(size_t)MROWS * NQKV];
__device__ bf16  g_Ohi[(size_t)MROWS * DM];
__device__ bf16  g_Olo[(size_t)MROWS * DM];

// ---------------- weight prep: transposed [n][k] hi/lo split ----------------
__global__ void prep_w_kernel(const float* __restrict__ Wq, const float* __restrict__ bq,
                              const float* __restrict__ Wk, const float* __restrict__ bk,
                              const float* __restrict__ Wv, const float* __restrict__ bv,
                              const float* __restrict__ Wfc)
{
    int i = blockIdx.x * blockDim.x + threadIdx.x;
    int stride = gridDim.x * blockDim.x;
    // g_Wqkv[j][d] = W_sec[h][d][e],  j = sec*256 + h*64 + e
    for (int idx = i; idx < NQKV * DM; idx += stride) {
        int j = idx >> 8, d = idx & 255;
        int sec = j >> 8;            // 0=q,1=k,2=v
        int h = (j & 255) >> 6;
        int e = j & 63;
        const float* W = (sec == 0) ? Wq : ((sec == 1) ? Wk : Wv);
        float w = W[(h * DM + d) * DHD + e];
        bf16 hi = __float2bfloat16(w);
        g_Wqkv_hi[idx] = hi;
        g_Wqkv_lo[idx] = __float2bfloat16(w - __bfloat162float(hi));
    }
    // g_Wfc[n][k] = Wfc[k][n]
    for (int idx = i; idx < DM * DM; idx += stride) {
        int n = idx >> 8, k = idx & 255;
        float w = Wfc[k * DM + n];
        bf16 hi = __float2bfloat16(w);
        g_Wfc_hi[idx] = hi;
        g_Wfc_lo[idx] = __float2bfloat16(w - __bfloat162float(hi));
    }
    for (int idx = i; idx < NQKV; idx += stride) {
        int sec = idx >> 8;
        int h = (idx & 255) >> 6;
        int e = idx & 63;
        const float* bsrc = (sec == 0) ? bq : ((sec == 1) ? bk : bv);
        g_bqkv[idx] = bsrc[h * DHD + e];
    }
}

// ---------------- mma / ldmatrix helpers ----------------
__device__ __forceinline__ void mma_bf16(float c[4], const unsigned a[4], unsigned b0, unsigned b1)
{
    asm volatile(
        "mma.sync.aligned.m16n8k16.row.col.f32.bf16.bf16.f32 "
        "{%0,%1,%2,%3}, {%4,%5,%6,%7}, {%8,%9}, {%0,%1,%2,%3};\n"
        : "+f"(c[0]), "+f"(c[1]), "+f"(c[2]), "+f"(c[3])
        : "r"(a[0]), "r"(a[1]), "r"(a[2]), "r"(a[3]), "r"(b0), "r"(b1));
}

__device__ __forceinline__ void ldsm4(unsigned r[4], unsigned addr)
{
    asm volatile("ldmatrix.sync.aligned.m8n8.x4.shared.b16 {%0,%1,%2,%3}, [%4];"
                 : "=r"(r[0]), "=r"(r[1]), "=r"(r[2]), "=r"(r[3]) : "r"(addr));
}

// ---------------- split-3 GEMM: C[M,NTOT] = A(hi+lo) @ B(hi+lo)^T + bias ----------------
// CTA tile 128x128, K-chunks of 64, 8 warps (4 M x 2 N), warp tile 32x64.
#define SROW 72   // padded smem row (bf16) for 64-wide k-chunk; 144B pitch -> ldsm conflict-free
#define SMEM_GEMM_BYTES (4 * 128 * SROW * 2)

template<int NTOT, bool FIRST>
__global__ void __launch_bounds__(256, 2)
gemm_split3_kernel(const float* __restrict__ Xf, const float* __restrict__ bias_in,
                   float* __restrict__ C_out)
{
    extern __shared__ bf16 smem[];
    bf16* sAh = smem;
    bf16* sAl = sAh + 128 * SROW;
    bf16* sBh = sAl + 128 * SROW;
    bf16* sBl = sBh + 128 * SROW;

    const bf16* __restrict__ Ah = g_Ohi;   // used when !FIRST
    const bf16* __restrict__ Al = g_Olo;
    const bf16* __restrict__ Bh = FIRST ? g_Wqkv_hi : g_Wfc_hi;
    const bf16* __restrict__ Bl = FIRST ? g_Wqkv_lo : g_Wfc_lo;
    const float* __restrict__ bias = FIRST ? g_bqkv : bias_in;
    float* __restrict__ C = FIRST ? g_QKV : C_out;

    const int tid = threadIdx.x;
    const int warp = tid >> 5, lane = tid & 31;
    const int gid = lane >> 2, tig = lane & 3;
    const int wm = (warp & 3) * 32;
    const int wn = (warp >> 2) * 64;
    const size_t m0 = (size_t)blockIdx.y * 128;
    const int n0 = blockIdx.x * 128;

    const unsigned uAh = (unsigned)__cvta_generic_to_shared(sAh);
    const unsigned uAl = (unsigned)__cvta_generic_to_shared(sAl);
    const unsigned uBh = (unsigned)__cvta_generic_to_shared(sBh);
    const unsigned uBl = (unsigned)__cvta_generic_to_shared(sBl);

    float acc[2][8][4];
    #pragma unroll
    for (int a = 0; a < 2; a++)
        #pragma unroll
        for (int b = 0; b < 8; b++)
            #pragma unroll
            for (int c = 0; c < 4; c++) acc[a][b][c] = 0.f;

    for (int kc = 0; kc < DM; kc += 64) {
        // ---- stage A tile [128 x 64] ----
        if (FIRST) {
            // fp32 x -> hi/lo bf16 conversion in-flight
            #pragma unroll
            for (int u = tid; u < 2048; u += 256) {
                int row = u >> 4;
                int kk = (u & 15) * 4;
                float4 v = *(const float4*)&Xf[(m0 + row) * DM + kc + kk];
                bf16 hx = __float2bfloat16(v.x), hy = __float2bfloat16(v.y);
                bf16 hz = __float2bfloat16(v.z), hw = __float2bfloat16(v.w);
                union { __nv_bfloat162 h2[2]; uint2 u2; } ph, pl;
                ph.h2[0] = __nv_bfloat162(hx, hy);
                ph.h2[1] = __nv_bfloat162(hz, hw);
                pl.h2[0] = __nv_bfloat162(__float2bfloat16(v.x - __bfloat162float(hx)),
                                          __float2bfloat16(v.y - __bfloat162float(hy)));
                pl.h2[1] = __nv_bfloat162(__float2bfloat16(v.z - __bfloat162float(hz)),
                                          __float2bfloat16(v.w - __bfloat162float(hw)));
                *(uint2*)&sAh[row * SROW + kk] = ph.u2;
                *(uint2*)&sAl[row * SROW + kk] = pl.u2;
            }
        } else {
            #pragma unroll
            for (int u = tid; u < 1024; u += 256) {
                int row = u >> 3;
                int kk = (u & 7) * 8;
                size_t g = (m0 + row) * DM + kc + kk;
                *(float4*)&sAh[row * SROW + kk] = *(const float4*)&Ah[g];
                *(float4*)&sAl[row * SROW + kk] = *(const float4*)&Al[g];
            }
        }
        // ---- stage B tile [128 x 64] (weights pre-transposed [n][k]) ----
        #pragma unroll
        for (int u = tid; u < 1024; u += 256) {
            int row = u >> 3;
            int kk = (u & 7) * 8;
            size_t g = (size_t)(n0 + row) * DM + kc + kk;
            *(float4*)&sBh[row * SROW + kk] = *(const float4*)&Bh[g];
            *(float4*)&sBl[row * SROW + kk] = *(const float4*)&Bl[g];
        }
        __syncthreads();

        #pragma unroll
        for (int ks = 0; ks < 4; ks++) {
            const int kb = ks * 16;
            // A fragments via ldmatrix.x4: lanes 0-7 m0-7@kb, 8-15 m8-15@kb,
            // 16-23 m0-7@kb+8, 24-31 m8-15@kb+8  -> {a0,a1,a2,a3}
            const int arow = wm + (lane & 15);
            const int acol = kb + ((lane >> 4) << 3);
            unsigned ah[2][4], al[2][4];
            #pragma unroll
            for (int mt = 0; mt < 2; mt++) {
                unsigned off = (unsigned)(((arow + mt * 16) * SROW + acol) * 2);
                ldsm4(ah[mt], uAh + off);
                ldsm4(al[mt], uAl + off);
            }
            // B fragments: one x4 covers two n8 tiles (b0,b1 for nt even; b0,b1 for nt odd)
            const int brr = ((lane >> 4) << 3) + (lane & 7);
            const int bcol = kb + (((lane >> 3) & 1) << 3);
            #pragma unroll
            for (int np = 0; np < 4; np++) {
                unsigned off = (unsigned)(((wn + np * 16 + brr) * SROW + bcol) * 2);
                unsigned bh[4], bl[4];
                ldsm4(bh, uBh + off);
                ldsm4(bl, uBl + off);
                #pragma unroll
                for (int mt = 0; mt < 2; mt++) {
                    mma_bf16(acc[mt][2 * np],     ah[mt], bh[0], bh[1]);
                    mma_bf16(acc[mt][2 * np],     ah[mt], bl[0], bl[1]);
                    mma_bf16(acc[mt][2 * np],     al[mt], bh[0], bh[1]);
                    mma_bf16(acc[mt][2 * np + 1], ah[mt], bh[2], bh[3]);
                    mma_bf16(acc[mt][2 * np + 1], ah[mt], bl[2], bl[3]);
                    mma_bf16(acc[mt][2 * np + 1], al[mt], bh[2], bh[3]);
                }
            }
        }
        __syncthreads();
    }

    // epilogue: + bias, fp32 store
    #pragma unroll
    for (int mt = 0; mt < 2; mt++) {
        #pragma unroll
        for (int nt = 0; nt < 8; nt++) {
            int cn = n0 + wn + nt * 8 + tig * 2;
            float b0 = bias[cn], b1 = bias[cn + 1];
            size_t r = m0 + wm + mt * 16 + gid;
            float2 v0 = make_float2(acc[mt][nt][0] + b0, acc[mt][nt][1] + b1);
            float2 v1 = make_float2(acc[mt][nt][2] + b0, acc[mt][nt][3] + b1);
            *(float2*)&C[r * NTOT + cn] = v0;
            *(float2*)&C[(r + 8) * NTOT + cn] = v1;
        }
    }
}

// ---------------- causal attention: one warp per (batch, head), register q, LDS.128 k/v ----------------
// k/v rows stored float4-interleaved (slot = i*4 + chunk) -> score/out reads are 4 distinct
// 16B segments x 8-lane broadcast = conflict-free.
__global__ void __launch_bounds__(256) attn_kernel()
{
    __shared__ float skv[8][2][TT][80];   // [warp][k/v][s][slot floats], 40KB

    const int warp = threadIdx.x >> 5, lane = threadIdx.x & 31;
    const int task = blockIdx.x * 8 + warp;
    const int b = task >> 2, h = task & 3;

    const float* base = g_QKV + (size_t)b * TT * NQKV + h * DHD;
    const int t = lane >> 2;
    const int sb = lane & 3;

    // stage k,v: lane claims slot u of row s; global f = slot-inverse (self-inverse perm)
    #pragma unroll
    for (int j = 0; j < 4; j++) {
        int idx = j * 32 + lane;          // 128 float4 slots (8 rows x 16)
        int s = idx >> 4;
        int u = idx & 15;
        int f = ((u & 3) << 2) | (u >> 2);
        float4 kk = *(const float4*)&base[s * NQKV + 256 + f * 4];
        float4 vv = *(const float4*)&base[s * NQKV + 512 + f * 4];
        ((float4*)&skv[warp][0][s][0])[u] = kk;
        ((float4*)&skv[warp][1][s][0])[u] = vv;
    }
    // q chunk in registers
    float4 q4[4];
    #pragma unroll
    for (int i = 0; i < 4; i++)
        q4[i] = *(const float4*)&base[t * NQKV + sb * 16 + i * 4];
    __syncwarp();

    // scores: partial dot over this lane's 16-e chunk, for all 8 s
    float sc[TT];
    #pragma unroll
    for (int s = 0; s < TT; s++) {
        float p = 0.f;
        #pragma unroll
        for (int i = 0; i < 4; i++) {
            float4 kk = ((const float4*)&skv[warp][0][s][0])[i * 4 + sb];
            p += q4[i].x * kk.x + q4[i].y * kk.y + q4[i].z * kk.z + q4[i].w * kk.w;
        }
        sc[s] = p;
    }
    // reduce over the 4 sb lanes (same t) -> every lane holds the full score row
    #pragma unroll
    for (int s = 0; s < TT; s++) {
        sc[s] += __shfl_xor_sync(0xffffffffu, sc[s], 1);
        sc[s] += __shfl_xor_sync(0xffffffffu, sc[s], 2);
        sc[s] = (s <= t) ? sc[s] * 0.125f : -1e30f;   // scale 1/sqrt(64), causal mask
    }
    // softmax entirely in registers
    float m = sc[0];
    #pragma unroll
    for (int s = 1; s < TT; s++) m = fmaxf(m, sc[s]);
    float wsum = 0.f;
    float wei[TT];
    #pragma unroll
    for (int s = 0; s < TT; s++) { wei[s] = __expf(sc[s] - m); wsum += wei[s]; }
    float inv = 1.0f / wsum;
    #pragma unroll
    for (int s = 0; s < TT; s++) wei[s] *= inv;

    // out: lane's 16 cols, hi/lo bf16 store
    const size_t orow = ((size_t)b * TT + t) * DM + h * DHD + sb * 16;
    #pragma unroll
    for (int i = 0; i < 4; i++) {
        float4 acc = make_float4(0.f, 0.f, 0.f, 0.f);
        #pragma unroll
        for (int s = 0; s < TT; s++) {
            float4 vv = ((const float4*)&skv[warp][1][s][0])[i * 4 + sb];
            acc.x += wei[s] * vv.x; acc.y += wei[s] * vv.y;
            acc.z += wei[s] * vv.z; acc.w += wei[s] * vv.w;
        }
        bf16 hx = __float2bfloat16(acc.x), hy = __float2bfloat16(acc.y);
        bf16 hz = __float2bfloat16(acc.z), hw = __float2bfloat16(acc.w);
        union { __nv_bfloat162 h2[2]; uint2 u2; } ph, pl;
        ph.h2[0] = __nv_bfloat162(hx, hy);
        ph.h2[1] = __nv_bfloat162(hz, hw);
        pl.h2[0] = __nv_bfloat162(__float2bfloat16(acc.x - __bfloat162float(hx)),
                                  __float2bfloat16(acc.y - __bfloat162float(hy)));
        pl.h2[1] = __nv_bfloat162(__float2bfloat16(acc.z - __bfloat162float(hz)),
                                  __float2bfloat16(acc.w - __bfloat162float(hw)));
        *(uint2*)&g_Ohi[orow + i * 4] = ph.u2;
        *(uint2*)&g_Olo[orow + i * 4] = pl.u2;
    }
}

// ---------------- launch ----------------
extern "C" void kernel_launch(void* const* d_in, const int* in_sizes, int n_in,
                              void* d_out, int out_size)
{
    const float* x   = (const float*)d_in[0];
    const float* Wq  = (const float*)d_in[1];
    const float* bq  = (const float*)d_in[2];
    const float* Wk  = (const float*)d_in[3];
    const float* bk  = (const float*)d_in[4];
    const float* Wv  = (const float*)d_in[5];
    const float* bv  = (const float*)d_in[6];
    const float* Wfc = (const float*)d_in[7];
    const float* bfc = (const float*)d_in[8];
    float* out = (float*)d_out;

    cudaFuncSetAttribute(gemm_split3_kernel<NQKV, true>,
                         cudaFuncAttributeMaxDynamicSharedMemorySize, SMEM_GEMM_BYTES);
    cudaFuncSetAttribute(gemm_split3_kernel<DM, false>,
                         cudaFuncAttributeMaxDynamicSharedMemorySize, SMEM_GEMM_BYTES);

    prep_w_kernel<<<192, 256>>>(Wq, bq, Wk, bk, Wv, bv, Wfc);

    // GEMM1: QKV = split(x) @ Wqkv + bqkv (x split fused into A-staging)
    gemm_split3_kernel<NQKV, true>
        <<<dim3(NQKV / 128, MROWS / 128), 256, SMEM_GEMM_BYTES>>>(x, nullptr, nullptr);

    // attention: 8 (batch,head) tasks per CTA (one per warp)
    attn_kernel<<<(NBATCH * NH) / 8, 256>>>();

    // GEMM2: out = split(O) @ Wfc + bfc
    gemm_split3_kernel<DM, false>
        <<<dim3(DM / 128, MROWS / 128), 256, SMEM_GEMM_BYTES>>>(nullptr, bfc, out);
}